// round 7
// baseline (speedup 1.0000x reference)
#include <cuda_runtime.h>

#define FULL 0xFFFFFFFFu
typedef unsigned long long ull;

// Precomputed gate parameters (weights are batch-uniform):
//   g_tau[0..39]  = tan(jet_w/2),  g_tau[40..43] = tan(ele_w/2),
//   g_tau[44..47] = tan(mu_w/2)
//   g_scale[0..2] = (prod cos(w/2))^2 for jet / ele / mu
//   g_met[0..1]   = sin(met_w), cos(met_w)
__device__ float g_tau[48];
__device__ float g_scale[3];
__device__ float g_met[2];

__global__ void prep_kernel(const float* __restrict__ met_w,
                            const float* __restrict__ ele_w,
                            const float* __restrict__ mu_w,
                            const float* __restrict__ jet_w) {
    if (threadIdx.x == 0) {
        float p = 1.f;
        for (int i = 0; i < 40; i++) {
            float s, c; __sincosf(0.5f * jet_w[i], &s, &c);
            g_tau[i] = __fdividef(s, c); p *= c;
        }
        g_scale[0] = p * p;
        p = 1.f;
        for (int i = 0; i < 4; i++) {
            float s, c; __sincosf(0.5f * ele_w[i], &s, &c);
            g_tau[40 + i] = __fdividef(s, c); p *= c;
        }
        g_scale[1] = p * p;
        p = 1.f;
        for (int i = 0; i < 4; i++) {
            float s, c; __sincosf(0.5f * mu_w[i], &s, &c);
            g_tau[44 + i] = __fdividef(s, c); p *= c;
        }
        g_scale[2] = p * p;
        float s, c; __sincosf(met_w[0], &s, &c);
        g_met[0] = s; g_met[1] = c;
    }
}

// ---------- packed f32x2 helpers (Blackwell paired-FP32 path) ----------
__device__ __forceinline__ ull pack2(float x, float y) {
    ull r; asm("mov.b64 %0,{%1,%2};" : "=l"(r) : "f"(x), "f"(y)); return r;
}
__device__ __forceinline__ float2 unpack2(ull v) {
    float2 r; asm("mov.b64 {%0,%1},%2;" : "=f"(r.x), "=f"(r.y) : "l"(v)); return r;
}
__device__ __forceinline__ ull f2fma(ull a, ull b, ull c) {  // a*b + c
    ull d; asm("fma.rn.f32x2 %0,%1,%2,%3;" : "=l"(d) : "l"(a), "l"(b), "l"(c)); return d;
}

__device__ __forceinline__ float2 cmul(float2 a, float2 b) {
    return make_float2(fmaf(a.x, b.x, -a.y * b.y), fmaf(a.x, b.y, a.y * b.x));
}

// Column 0 of RZ(phi)*RY(pt)*RX(eta) applied to |0>.
__device__ __forceinline__ void wire_u(float pt, float eta, float phi,
                                       float2& u0, float2& u1) {
    float se, ce, sy, cy, sz, cz;
    __sincosf(0.5f * eta, &se, &ce);
    __sincosf(0.5f * pt, &sy, &cy);
    __sincosf(0.5f * phi, &sz, &cz);
    float2 b0 = make_float2(cy * ce, sy * se);
    float2 b1 = make_float2(sy * ce, -cy * se);
    u0 = cmul(make_float2(cz, -sz), b0);
    u1 = cmul(make_float2(cz, sz), b1);
}

// width-16 broadcast of a float2 held lane-wise
__device__ __forceinline__ float2 bc16(float vx, float vy, int src) {
    float2 r;
    r.x = __shfl_sync(FULL, vx, src, 16);
    r.y = __shfl_sync(FULL, vy, src, 16);
    return r;
}

// 4-qubit QAE block (ele / mu): latent=[0,1], trash=[2,3], depth=1.
// RY gates tau-factorized; overall scale (prod cos)^2 passed in.
__device__ __forceinline__ void sim4(const float* __restrict__ xr,
                                     int pt_off, int eta_off, int phi_off,
                                     const float* __restrict__ taus, float sc2,
                                     float& o0, float& o1) {
    float2 u0[4], u1[4];
#pragma unroll
    for (int k = 0; k < 4; k++)
        wire_u(xr[pt_off + k], xr[eta_off + k], xr[phi_off + k], u0[k], u1[k]);

    float2 a[16];
    a[0] = make_float2(1.f, 0.f);
#pragma unroll
    for (int j = 0; j < 4; j++) {
        int wk = 3 - j;
#pragma unroll
        for (int t = 0; t < (1 << j); t++) {
            a[t + (1 << j)] = cmul(a[t], u1[wk]);
            a[t]            = cmul(a[t], u0[wk]);
        }
    }
    // perm1: bits {3,2} ^= parity(bits {1,0})
    {
        float2 t;
        t = a[1];  a[1]  = a[13]; a[13] = t;
        t = a[2];  a[2]  = a[14]; a[14] = t;
        t = a[5];  a[5]  = a[9];  a[9]  = t;
        t = a[6];  a[6]  = a[10]; a[10] = t;
    }
#pragma unroll
    for (int k = 0; k < 4; k++) {
        float tau = taus[k];
        int m = 1 << (3 - k);
#pragma unroll
        for (int i = 0; i < 16; i++) {
            if (!(i & m)) {
                int i1 = i | m;
                float2 a0 = a[i], a1v = a[i1];
                a[i]  = make_float2(fmaf(-tau, a1v.x, a0.x), fmaf(-tau, a1v.y, a0.y));
                a[i1] = make_float2(fmaf(tau, a0.x, a1v.x), fmaf(tau, a0.y, a1v.y));
            }
        }
    }
    // perm2: bits {1,0} ^= parity(bits {3,2})
    {
        float2 t;
        t = a[4]; a[4] = a[7];  a[7]  = t;
        t = a[5]; a[5] = a[6];  a[6]  = t;
        t = a[8]; a[8] = a[11]; a[11] = t;
        t = a[9]; a[9] = a[10]; a[10] = t;
    }
    float r0 = 0.f, r1 = 0.f;
#pragma unroll
    for (int i = 0; i < 16; i++) {
        float p = fmaf(a[i].x, a[i].x, a[i].y * a[i].y);
        r0 += ((i >> 1) & 1) ? -p : p;
        r1 += (i & 1) ? -p : p;
    }
    o0 = r0 * sc2;
    o1 = r1 * sc2;
}

// Gate emission order within a depth: interleave lane-bit (SHFL) gates with
// register-bit (FMA) gates so MIO and FMA pipes overlap. Gates on distinct
// wires commute, so any order is correct.
__constant__ int c_korder[10] = {6, 0, 1, 7, 2, 3, 8, 4, 5, 9};

__global__ __launch_bounds__(32, 15)
void qae_kernel(const float* __restrict__ x,
                float* __restrict__ out,
                int B, int nJetBlocks) {
    if ((int)blockIdx.x < nJetBlocks) {
        // ================= jet: 2 events per warp, n=10 qubits =================
        // Amplitude index (10 bits): lane bits 0..3 (sub) = trash wires 9..6;
        // register bits r0..r5 = latent wires 5..0. Lane bit 4 = event select.
        int warpId = blockIdx.x;             // one warp per block
        int lane = threadIdx.x & 31;
        int sub  = lane & 15;
        int half = lane >> 4;
        int event = warpId * 2 + half;
        int evc = event < B ? event : B - 1;        // clamp loads for odd B
        const float* xr = x + (size_t)evc * 56;

        // Per-wire encoding column: lanes sub 0..9 of each half compute; values
        // broadcast on demand via width-16 shfl.
        int kk = sub < 10 ? sub : 0;
        float2 myu0, myu1;
        wire_u(xr[26 + kk], xr[36 + kk], xr[46 + kk], myu0, myu1);

        // Lane-bit part of the tensor product: sub bit m <-> trash wire 9-m.
        float2 pl = make_float2(1.f, 0.f);
#pragma unroll
        for (int m = 0; m < 4; m++) {
            int w = 9 - m;
            float2 b0 = bc16(myu0.x, myu0.y, w);
            float2 b1 = bc16(myu1.x, myu1.y, w);
            float2 sel = ((sub >> m) & 1) ? b1 : b0;
            pl = cmul(pl, sel);
        }

        bool p1 = (__popc(sub) & 1) != 0;   // parity of trash bits

        // Register-bit part via doubling: reg bit j <-> latent wire 5-j.
        // Depth-0 perm1 (flip all latent bits if p1) folded in: u roles swap.
        ull a[64];
        a[0] = pack2(pl.x, pl.y);
#pragma unroll
        for (int j = 0; j < 6; j++) {
            int w = 5 - j;
            float2 b0 = bc16(myu0.x, myu0.y, w);
            float2 b1 = bc16(myu1.x, myu1.y, w);
            float2 f0 = p1 ? b1 : b0;
            float2 f1 = p1 ? b0 : b1;
#pragma unroll
            for (int t = 0; t < (1 << j); t++) {
                float2 at = unpack2(a[t]);
                float2 hi = cmul(at, f1);
                float2 lo = cmul(at, f0);
                a[t + (1 << j)] = pack2(hi.x, hi.y);
                a[t]            = pack2(lo.x, lo.y);
            }
        }

#pragma unroll 1
        for (int d = 0; d < 4; d++) {
            // perm1 (d>0; depth-0 folded into encoding): flip all 6 register
            // (latent) bits if p1 -> conditional register-pair swap.
            if (d) {
#pragma unroll
                for (int r = 0; r < 32; r++) {
                    ull t0 = a[r], t1 = a[63 - r];
                    a[r]      = p1 ? t1 : t0;
                    a[63 - r] = p1 ? t0 : t1;
                }
            }
            // RY(jet_w[d*10+k]) on wire k, tau-factorized (scale deferred).
            // Emitted in interleaved order (c_korder) to overlap SHFL with FMA.
#pragma unroll
            for (int kq = 0; kq < 10; kq++) {
                int k = c_korder[kq];
                float tau = g_tau[d * 10 + k];
                if (k < 6) {                     // register bit j = 5-k
                    int m = 1 << (5 - k);
                    ull tq = pack2(tau, tau), ntq = pack2(-tau, -tau);
#pragma unroll
                    for (int r = 0; r < 64; r++) {
                        if (!(r & m)) {
                            int r1 = r | m;
                            ull a0 = a[r];
                            a[r]  = f2fma(ntq, a[r1], a0);
                            a[r1] = f2fma(tq, a0, a[r1]);
                        }
                    }
                } else {                         // lane bit (9-k): shfl pairing
                    int mb = 1 << (9 - k);
                    float tt = (sub & mb) ? tau : -tau;
                    ull t2 = pack2(tt, tt);
#pragma unroll
                    for (int r = 0; r < 64; r++) {
                        ull p = __shfl_xor_sync(FULL, a[r], mb);
                        a[r] = f2fma(t2, p, a[r]);
                    }
                }
            }
            // perm2: flip trash (lane) bits where popc(r) odd. Skipped on the
            // final depth (folded into the <Z> sign as S_even - S_odd).
            if (d != 3) {
#pragma unroll
                for (int r = 0; r < 64; r++) {
                    if (__popc(r) & 1)
                        a[r] = __shfl_xor_sync(FULL, a[r], 15);
                }
            }
        }

        // <Z> on trash wires 6..9 (sub bits 3..0), final perm2 + global scale
        // absorbed: Z_b = sign_b(sub) * (S_even - S_odd) * (prod cos)^2.
        ull ae = pack2(0.f, 0.f), ao = pack2(0.f, 0.f);
#pragma unroll
        for (int r = 0; r < 64; r++) {
            if (__popc(r) & 1) ao = f2fma(a[r], a[r], ao);
            else               ae = f2fma(a[r], a[r], ae);
        }
        float2 fe = unpack2(ae), fo = unpack2(ao);
        float sd = ((fe.x + fe.y) - (fo.x + fo.y)) * g_scale[0];

        // Signed Walsh butterfly over the 4 sub bits: after 4 levels, lane s
        // holds sum_t (-1)^{popc(s&t)} sd(t). We need s in {1,2,4,8}:
        // s = 1<<bit gives <Z> for trash bit 'bit' (wire 9-bit... wire 6+(3-bit)).
#pragma unroll
        for (int off = 1; off <= 8; off <<= 1) {
            float p = __shfl_xor_sync(FULL, sd, off);
            sd = (sub & off) ? (p - sd) : (sd + p);
        }
        if (__popc(sub) == 1 && event < B) {
            // sub = 1<<bit; output index j = 3 - bit
            int bit = 31 - __clz(sub);
            out[(size_t)5 * B + (size_t)event * 4 + (3 - bit)] = sd;
        }
    } else {
        // ---------------- met + ele + mu: one thread per event ----------------
        int e = (blockIdx.x - nJetBlocks) * 32 + threadIdx.x;
        if (e >= B) return;
        const float* xr = x + (size_t)e * 56;

        {   // met (n=1): <Z> = cos(w)cos(pt) - sin(w)sin(pt)cos(phi)
            float sp, cp;
            __sincosf(xr[0], &sp, &cp);
            float cf = __cosf(xr[1]);
            out[e] = g_met[1] * cp - g_met[0] * sp * cf;
        }
        float o0, o1;
        sim4(xr, 2, 6, 10, &g_tau[40], g_scale[1], o0, o1);
        out[(size_t)B + (size_t)e * 2 + 0] = o0;
        out[(size_t)B + (size_t)e * 2 + 1] = o1;
        sim4(xr, 14, 18, 22, &g_tau[44], g_scale[2], o0, o1);
        out[(size_t)3 * B + (size_t)e * 2 + 0] = o0;
        out[(size_t)3 * B + (size_t)e * 2 + 1] = o1;
    }
}

extern "C" void kernel_launch(void* const* d_in, const int* in_sizes, int n_in,
                              void* d_out, int out_size) {
    const float* x     = (const float*)d_in[0];
    const float* met_w = (const float*)d_in[1];
    const float* ele_w = (const float*)d_in[2];
    const float* mu_w  = (const float*)d_in[3];
    const float* jet_w = (const float*)d_in[4];
    int B = in_sizes[0] / 56;
    int nJetBlocks = (B + 1) / 2;          // 1 warp/block, 2 events/warp
    int nSmallBlocks = (B + 31) / 32;      // 1 thread/event for met/ele/mu
    prep_kernel<<<1, 32>>>(met_w, ele_w, mu_w, jet_w);
    qae_kernel<<<nJetBlocks + nSmallBlocks, 32>>>(
        x, (float*)d_out, B, nJetBlocks);
}

// round 8
// speedup vs baseline: 7.3445x; 7.3445x over previous
#include <cuda_runtime.h>

#define FULL 0xFFFFFFFFu
typedef unsigned long long ull;

// Precomputed gate parameters (weights are batch-uniform):
//   g_tau[0..39]  = tan(jet_w/2),  g_tau[40..43] = tan(ele_w/2),
//   g_tau[44..47] = tan(mu_w/2)
//   g_scale[0..2] = (prod cos(w/2))^2 for jet / ele / mu
//   g_met[0..1]   = sin(met_w), cos(met_w)
__device__ float g_tau[48];
__device__ float g_scale[3];
__device__ float g_met[2];

__global__ void prep_kernel(const float* __restrict__ met_w,
                            const float* __restrict__ ele_w,
                            const float* __restrict__ mu_w,
                            const float* __restrict__ jet_w) {
    if (threadIdx.x == 0) {
        float p = 1.f;
        for (int i = 0; i < 40; i++) {
            float s, c; __sincosf(0.5f * jet_w[i], &s, &c);
            g_tau[i] = __fdividef(s, c); p *= c;
        }
        g_scale[0] = p * p;
        p = 1.f;
        for (int i = 0; i < 4; i++) {
            float s, c; __sincosf(0.5f * ele_w[i], &s, &c);
            g_tau[40 + i] = __fdividef(s, c); p *= c;
        }
        g_scale[1] = p * p;
        p = 1.f;
        for (int i = 0; i < 4; i++) {
            float s, c; __sincosf(0.5f * mu_w[i], &s, &c);
            g_tau[44 + i] = __fdividef(s, c); p *= c;
        }
        g_scale[2] = p * p;
        float s, c; __sincosf(met_w[0], &s, &c);
        g_met[0] = s; g_met[1] = c;
    }
}

// ---------- packed f32x2 helpers (Blackwell paired-FP32 path) ----------
__device__ __forceinline__ ull pack2(float x, float y) {
    ull r; asm("mov.b64 %0,{%1,%2};" : "=l"(r) : "f"(x), "f"(y)); return r;
}
__device__ __forceinline__ float2 unpack2(ull v) {
    float2 r; asm("mov.b64 {%0,%1},%2;" : "=f"(r.x), "=f"(r.y) : "l"(v)); return r;
}
__device__ __forceinline__ ull f2fma(ull a, ull b, ull c) {  // a*b + c
    ull d; asm("fma.rn.f32x2 %0,%1,%2,%3;" : "=l"(d) : "l"(a), "l"(b), "l"(c)); return d;
}

__device__ __forceinline__ float2 cmul(float2 a, float2 b) {
    return make_float2(fmaf(a.x, b.x, -a.y * b.y), fmaf(a.x, b.y, a.y * b.x));
}

// Column 0 of RZ(phi)*RY(pt)*RX(eta) applied to |0>.
__device__ __forceinline__ void wire_u(float pt, float eta, float phi,
                                       float2& u0, float2& u1) {
    float se, ce, sy, cy, sz, cz;
    __sincosf(0.5f * eta, &se, &ce);
    __sincosf(0.5f * pt, &sy, &cy);
    __sincosf(0.5f * phi, &sz, &cz);
    float2 b0 = make_float2(cy * ce, sy * se);
    float2 b1 = make_float2(sy * ce, -cy * se);
    u0 = cmul(make_float2(cz, -sz), b0);
    u1 = cmul(make_float2(cz, sz), b1);
}

// width-16 broadcast of a float2 held lane-wise
__device__ __forceinline__ float2 bc16(float vx, float vy, int src) {
    float2 r;
    r.x = __shfl_sync(FULL, vx, src, 16);
    r.y = __shfl_sync(FULL, vy, src, 16);
    return r;
}

// 4-qubit QAE block (ele / mu): latent=[0,1], trash=[2,3], depth=1.
// RY gates tau-factorized; overall scale (prod cos)^2 passed in.
__device__ __forceinline__ void sim4(const float* __restrict__ xr,
                                     int pt_off, int eta_off, int phi_off,
                                     const float* __restrict__ taus, float sc2,
                                     float& o0, float& o1) {
    float2 u0[4], u1[4];
#pragma unroll
    for (int k = 0; k < 4; k++)
        wire_u(xr[pt_off + k], xr[eta_off + k], xr[phi_off + k], u0[k], u1[k]);

    float2 a[16];
    a[0] = make_float2(1.f, 0.f);
#pragma unroll
    for (int j = 0; j < 4; j++) {
        int wk = 3 - j;
#pragma unroll
        for (int t = 0; t < (1 << j); t++) {
            a[t + (1 << j)] = cmul(a[t], u1[wk]);
            a[t]            = cmul(a[t], u0[wk]);
        }
    }
    // perm1: bits {3,2} ^= parity(bits {1,0})
    {
        float2 t;
        t = a[1];  a[1]  = a[13]; a[13] = t;
        t = a[2];  a[2]  = a[14]; a[14] = t;
        t = a[5];  a[5]  = a[9];  a[9]  = t;
        t = a[6];  a[6]  = a[10]; a[10] = t;
    }
#pragma unroll
    for (int k = 0; k < 4; k++) {
        float tau = taus[k];
        int m = 1 << (3 - k);
#pragma unroll
        for (int i = 0; i < 16; i++) {
            if (!(i & m)) {
                int i1 = i | m;
                float2 a0 = a[i], a1v = a[i1];
                a[i]  = make_float2(fmaf(-tau, a1v.x, a0.x), fmaf(-tau, a1v.y, a0.y));
                a[i1] = make_float2(fmaf(tau, a0.x, a1v.x), fmaf(tau, a0.y, a1v.y));
            }
        }
    }
    // perm2: bits {1,0} ^= parity(bits {3,2})
    {
        float2 t;
        t = a[4]; a[4] = a[7];  a[7]  = t;
        t = a[5]; a[5] = a[6];  a[6]  = t;
        t = a[8]; a[8] = a[11]; a[11] = t;
        t = a[9]; a[9] = a[10]; a[10] = t;
    }
    float r0 = 0.f, r1 = 0.f;
#pragma unroll
    for (int i = 0; i < 16; i++) {
        float p = fmaf(a[i].x, a[i].x, a[i].y * a[i].y);
        r0 += ((i >> 1) & 1) ? -p : p;
        r1 += (i & 1) ? -p : p;
    }
    o0 = r0 * sc2;
    o1 = r1 * sc2;
}

__global__ __launch_bounds__(64, 6)
void qae_kernel(const float* __restrict__ x,
                float* __restrict__ out,
                int B, int nJetBlocks) {
    if ((int)blockIdx.x < nJetBlocks) {
        // ================= jet: 2 events per warp, n=10 qubits =================
        // Amplitude index (10 bits): lane bits 0..3 (sub) = trash wires 9..6;
        // register bits r0..r5 = latent wires 5..0. Lane bit 4 = event select.
        int warpId = blockIdx.x * 2 + (threadIdx.x >> 5);
        if (warpId * 2 >= B) return;
        int lane = threadIdx.x & 31;
        int sub  = lane & 15;
        int half = lane >> 4;
        int event = warpId * 2 + half;
        int evc = event < B ? event : B - 1;        // clamp loads for odd B
        const float* xr = x + (size_t)evc * 56;

        // Per-wire encoding column: lanes sub 0..9 of each half compute; values
        // broadcast on demand via width-16 shfl.
        int kk = sub < 10 ? sub : 0;
        float2 myu0, myu1;
        wire_u(xr[26 + kk], xr[36 + kk], xr[46 + kk], myu0, myu1);

        // Lane-bit part of the tensor product: sub bit m <-> trash wire 9-m.
        float2 pl = make_float2(1.f, 0.f);
#pragma unroll
        for (int m = 0; m < 4; m++) {
            int w = 9 - m;
            float2 b0 = bc16(myu0.x, myu0.y, w);
            float2 b1 = bc16(myu1.x, myu1.y, w);
            float2 sel = ((sub >> m) & 1) ? b1 : b0;
            pl = cmul(pl, sel);
        }

        bool p1 = (__popc(sub) & 1) != 0;   // parity of trash bits

        // Register-bit part via doubling: reg bit j <-> latent wire 5-j.
        // Depth-0 perm1 (flip all latent bits if p1) folded in: u roles swap.
        ull a[64];
        a[0] = pack2(pl.x, pl.y);
#pragma unroll
        for (int j = 0; j < 6; j++) {
            int w = 5 - j;
            float2 b0 = bc16(myu0.x, myu0.y, w);
            float2 b1 = bc16(myu1.x, myu1.y, w);
            float2 f0 = p1 ? b1 : b0;
            float2 f1 = p1 ? b0 : b1;
#pragma unroll
            for (int t = 0; t < (1 << j); t++) {
                float2 at = unpack2(a[t]);
                float2 hi = cmul(at, f1);
                float2 lo = cmul(at, f0);
                a[t + (1 << j)] = pack2(hi.x, hi.y);
                a[t]            = pack2(lo.x, lo.y);
            }
        }

        // Gate emission order within a depth: interleave lane-bit (SHFL) gates
        // with register-bit (FMA) gates so the MIO and FMA pipes overlap.
        // Gates act on distinct wires, so any order is correct.
        const int korder[10] = {6, 0, 1, 7, 2, 3, 8, 4, 5, 9};

#pragma unroll 1
        for (int d = 0; d < 4; d++) {
            // perm1 (d>0; depth-0 folded into encoding): flip all 6 register
            // (latent) bits if p1 -> conditional register-pair swap.
            if (d) {
#pragma unroll
                for (int r = 0; r < 32; r++) {
                    ull t0 = a[r], t1 = a[63 - r];
                    a[r]      = p1 ? t1 : t0;
                    a[63 - r] = p1 ? t0 : t1;
                }
            }
            // RY(jet_w[d*10+k]) on wire k, tau-factorized (scale deferred).
#pragma unroll
            for (int kq = 0; kq < 10; kq++) {
                int k = korder[kq];
                float tau = g_tau[d * 10 + k];
                if (k < 6) {                     // register bit j = 5-k
                    int m = 1 << (5 - k);
                    ull tq = pack2(tau, tau), ntq = pack2(-tau, -tau);
#pragma unroll
                    for (int r = 0; r < 64; r++) {
                        if (!(r & m)) {
                            int r1 = r | m;
                            ull a0 = a[r];
                            a[r]  = f2fma(ntq, a[r1], a0);
                            a[r1] = f2fma(tq, a0, a[r1]);
                        }
                    }
                } else {                         // lane bit (9-k): shfl pairing
                    int mb = 1 << (9 - k);
                    float tt = (sub & mb) ? tau : -tau;
                    ull t2 = pack2(tt, tt);
#pragma unroll
                    for (int r = 0; r < 64; r++) {
                        ull p = __shfl_xor_sync(FULL, a[r], mb);
                        a[r] = f2fma(t2, p, a[r]);
                    }
                }
            }
            // perm2: flip trash (lane) bits where popc(r) odd. Skipped on the
            // final depth (folded into the <Z> sign as S_even - S_odd).
            if (d != 3) {
#pragma unroll
                for (int r = 0; r < 64; r++) {
                    if (__popc(r) & 1)
                        a[r] = __shfl_xor_sync(FULL, a[r], 15);
                }
            }
        }

        // <Z> on trash wires 6..9 (sub bits 3..0), final perm2 + global scale
        // absorbed: Z_b = sign_b(sub) * (S_even - S_odd) * (prod cos)^2.
        ull ae = pack2(0.f, 0.f), ao = pack2(0.f, 0.f);
#pragma unroll
        for (int r = 0; r < 64; r++) {
            if (__popc(r) & 1) ao = f2fma(a[r], a[r], ao);
            else               ae = f2fma(a[r], a[r], ae);
        }
        float2 fe = unpack2(ae), fo = unpack2(ao);
        float sd = ((fe.x + fe.y) - (fo.x + fo.y)) * g_scale[0];

        // Signed Walsh butterfly over the 4 sub bits (width 16, per half):
        // after 4 levels, lane s holds sum_t (-1)^{popc(s&t)} sd(t).
        // Lanes with s = 1<<bit carry <Z> for trash lane-bit 'bit'.
#pragma unroll
        for (int off = 1; off <= 8; off <<= 1) {
            float p = __shfl_xor_sync(FULL, sd, off);
            sd = (sub & off) ? (p - sd) : (sd + p);
        }
        if (__popc(sub) == 1 && event < B) {
            int bit = 31 - __clz(sub);       // sub = 1<<bit; output j = 3-bit
            out[(size_t)5 * B + (size_t)event * 4 + (3 - bit)] = sd;
        }
    } else {
        // ---------------- met + ele + mu: one thread per event ----------------
        int e = (blockIdx.x - nJetBlocks) * 64 + threadIdx.x;
        if (e >= B) return;
        const float* xr = x + (size_t)e * 56;

        {   // met (n=1): <Z> = cos(w)cos(pt) - sin(w)sin(pt)cos(phi)
            float sp, cp;
            __sincosf(xr[0], &sp, &cp);
            float cf = __cosf(xr[1]);
            out[e] = g_met[1] * cp - g_met[0] * sp * cf;
        }
        float o0, o1;
        sim4(xr, 2, 6, 10, &g_tau[40], g_scale[1], o0, o1);
        out[(size_t)B + (size_t)e * 2 + 0] = o0;
        out[(size_t)B + (size_t)e * 2 + 1] = o1;
        sim4(xr, 14, 18, 22, &g_tau[44], g_scale[2], o0, o1);
        out[(size_t)3 * B + (size_t)e * 2 + 0] = o0;
        out[(size_t)3 * B + (size_t)e * 2 + 1] = o1;
    }
}

extern "C" void kernel_launch(void* const* d_in, const int* in_sizes, int n_in,
                              void* d_out, int out_size) {
    const float* x     = (const float*)d_in[0];
    const float* met_w = (const float*)d_in[1];
    const float* ele_w = (const float*)d_in[2];
    const float* mu_w  = (const float*)d_in[3];
    const float* jet_w = (const float*)d_in[4];
    int B = in_sizes[0] / 56;
    int nJetBlocks = (B + 3) / 4;          // 2 warps/block, 2 events/warp
    int nSmallBlocks = (B + 63) / 64;      // 1 thread/event for met/ele/mu
    prep_kernel<<<1, 32>>>(met_w, ele_w, mu_w, jet_w);
    qae_kernel<<<nJetBlocks + nSmallBlocks, 64>>>(
        x, (float*)d_out, B, nJetBlocks);
}

// round 9
// speedup vs baseline: 7.4081x; 1.0087x over previous
#include <cuda_runtime.h>

#define FULL 0xFFFFFFFFu
typedef unsigned long long ull;

// Precomputed gate parameters (weights are batch-uniform):
//   g_tau[0..39]  = tan(jet_w/2),  g_tau[40..43] = tan(ele_w/2),
//   g_tau[44..47] = tan(mu_w/2)
//   g_scale[0..2] = (prod cos(w/2))^2 for jet / ele / mu
//   g_met[0..1]   = sin(met_w), cos(met_w)
__device__ float g_tau[48];
__device__ float g_scale[3];
__device__ float g_met[2];

__global__ void prep_kernel(const float* __restrict__ met_w,
                            const float* __restrict__ ele_w,
                            const float* __restrict__ mu_w,
                            const float* __restrict__ jet_w) {
    if (threadIdx.x == 0) {
        float p = 1.f;
        for (int i = 0; i < 40; i++) {
            float s, c; __sincosf(0.5f * jet_w[i], &s, &c);
            g_tau[i] = __fdividef(s, c); p *= c;
        }
        g_scale[0] = p * p;
        p = 1.f;
        for (int i = 0; i < 4; i++) {
            float s, c; __sincosf(0.5f * ele_w[i], &s, &c);
            g_tau[40 + i] = __fdividef(s, c); p *= c;
        }
        g_scale[1] = p * p;
        p = 1.f;
        for (int i = 0; i < 4; i++) {
            float s, c; __sincosf(0.5f * mu_w[i], &s, &c);
            g_tau[44 + i] = __fdividef(s, c); p *= c;
        }
        g_scale[2] = p * p;
        float s, c; __sincosf(met_w[0], &s, &c);
        g_met[0] = s; g_met[1] = c;
    }
}

// ---------- packed f32x2 helpers (Blackwell paired-FP32 path) ----------
__device__ __forceinline__ ull pack2(float x, float y) {
    ull r; asm("mov.b64 %0,{%1,%2};" : "=l"(r) : "f"(x), "f"(y)); return r;
}
__device__ __forceinline__ float2 unpack2(ull v) {
    float2 r; asm("mov.b64 {%0,%1},%2;" : "=f"(r.x), "=f"(r.y) : "l"(v)); return r;
}
__device__ __forceinline__ ull f2fma(ull a, ull b, ull c) {  // a*b + c
    ull d; asm("fma.rn.f32x2 %0,%1,%2,%3;" : "=l"(d) : "l"(a), "l"(b), "l"(c)); return d;
}

__device__ __forceinline__ float2 cmul(float2 a, float2 b) {
    return make_float2(fmaf(a.x, b.x, -a.y * b.y), fmaf(a.x, b.y, a.y * b.x));
}

// Column 0 of RZ(phi)*RY(pt)*RX(eta) applied to |0>.
__device__ __forceinline__ void wire_u(float pt, float eta, float phi,
                                       float2& u0, float2& u1) {
    float se, ce, sy, cy, sz, cz;
    __sincosf(0.5f * eta, &se, &ce);
    __sincosf(0.5f * pt, &sy, &cy);
    __sincosf(0.5f * phi, &sz, &cz);
    float2 b0 = make_float2(cy * ce, sy * se);
    float2 b1 = make_float2(sy * ce, -cy * se);
    u0 = cmul(make_float2(cz, -sz), b0);
    u1 = cmul(make_float2(cz, sz), b1);
}

// width-16 broadcast of a float2 held lane-wise
__device__ __forceinline__ float2 bc16(float vx, float vy, int src) {
    float2 r;
    r.x = __shfl_sync(FULL, vx, src, 16);
    r.y = __shfl_sync(FULL, vy, src, 16);
    return r;
}

// 4-qubit QAE block (ele / mu): latent=[0,1], trash=[2,3], depth=1.
// RY gates tau-factorized; overall scale (prod cos)^2 passed in.
__device__ __forceinline__ void sim4(const float* __restrict__ xr,
                                     int pt_off, int eta_off, int phi_off,
                                     const float* __restrict__ taus, float sc2,
                                     float& o0, float& o1) {
    float2 u0[4], u1[4];
#pragma unroll
    for (int k = 0; k < 4; k++)
        wire_u(xr[pt_off + k], xr[eta_off + k], xr[phi_off + k], u0[k], u1[k]);

    float2 a[16];
    a[0] = make_float2(1.f, 0.f);
#pragma unroll
    for (int j = 0; j < 4; j++) {
        int wk = 3 - j;
#pragma unroll
        for (int t = 0; t < (1 << j); t++) {
            a[t + (1 << j)] = cmul(a[t], u1[wk]);
            a[t]            = cmul(a[t], u0[wk]);
        }
    }
    // perm1: bits {3,2} ^= parity(bits {1,0})
    {
        float2 t;
        t = a[1];  a[1]  = a[13]; a[13] = t;
        t = a[2];  a[2]  = a[14]; a[14] = t;
        t = a[5];  a[5]  = a[9];  a[9]  = t;
        t = a[6];  a[6]  = a[10]; a[10] = t;
    }
#pragma unroll
    for (int k = 0; k < 4; k++) {
        float tau = taus[k];
        int m = 1 << (3 - k);
#pragma unroll
        for (int i = 0; i < 16; i++) {
            if (!(i & m)) {
                int i1 = i | m;
                float2 a0 = a[i], a1v = a[i1];
                a[i]  = make_float2(fmaf(-tau, a1v.x, a0.x), fmaf(-tau, a1v.y, a0.y));
                a[i1] = make_float2(fmaf(tau, a0.x, a1v.x), fmaf(tau, a0.y, a1v.y));
            }
        }
    }
    // perm2: bits {1,0} ^= parity(bits {3,2})
    {
        float2 t;
        t = a[4]; a[4] = a[7];  a[7]  = t;
        t = a[5]; a[5] = a[6];  a[6]  = t;
        t = a[8]; a[8] = a[11]; a[11] = t;
        t = a[9]; a[9] = a[10]; a[10] = t;
    }
    float r0 = 0.f, r1 = 0.f;
#pragma unroll
    for (int i = 0; i < 16; i++) {
        float p = fmaf(a[i].x, a[i].x, a[i].y * a[i].y);
        r0 += ((i >> 1) & 1) ? -p : p;
        r1 += (i & 1) ? -p : p;
    }
    o0 = r0 * sc2;
    o1 = r1 * sc2;
}

__global__ __launch_bounds__(64, 6)
void qae_kernel(const float* __restrict__ x,
                float* __restrict__ out,
                int B, int nJetBlocks) {
    if ((int)blockIdx.x < nJetBlocks) {
        // ================= jet: 2 events per warp, n=10 qubits =================
        // Amplitude index (10 bits): lane bits 0..3 (sub) = trash wires 9..6;
        // register bits r0..r5 = latent wires 5..0. Lane bit 4 = event select.
        int warpId = blockIdx.x * 2 + (threadIdx.x >> 5);
        if (warpId * 2 >= B) return;
        int lane = threadIdx.x & 31;
        int sub  = lane & 15;
        int half = lane >> 4;
        int event = warpId * 2 + half;
        int evc = event < B ? event : B - 1;        // clamp loads for odd B
        const float* xr = x + (size_t)evc * 56;

        // Per-wire encoding column: lanes sub 0..9 of each half compute; values
        // broadcast on demand via width-16 shfl.
        int kk = sub < 10 ? sub : 0;
        float2 myu0, myu1;
        wire_u(xr[26 + kk], xr[36 + kk], xr[46 + kk], myu0, myu1);

        // Lane-bit part of the tensor product: sub bit m <-> trash wire 9-m.
        float2 pl = make_float2(1.f, 0.f);
#pragma unroll
        for (int m = 0; m < 4; m++) {
            int w = 9 - m;
            float2 b0 = bc16(myu0.x, myu0.y, w);
            float2 b1 = bc16(myu1.x, myu1.y, w);
            float2 sel = ((sub >> m) & 1) ? b1 : b0;
            pl = cmul(pl, sel);
        }

        bool p1 = (__popc(sub) & 1) != 0;   // parity of trash bits

        // Register-bit part via doubling: reg bit j <-> latent wire 5-j.
        // Two folds applied to the factors before the product is built:
        //  (a) depth-0 perm1 (flip all latent bits if p1): swap factor roles.
        //  (b) depth-0 RY on each latent wire: acts factor-wise on the product
        //      state. With roles swapped (p1), the tau sign flips:
        //      f0' = f0 + s*tau*f1, f1' = f1 - s*tau*f0,  s = p1 ? +1 : -1.
        ull a[64];
        a[0] = pack2(pl.x, pl.y);
#pragma unroll
        for (int j = 0; j < 6; j++) {
            int w = 5 - j;
            float2 b0 = bc16(myu0.x, myu0.y, w);
            float2 b1 = bc16(myu1.x, myu1.y, w);
            float2 f0 = p1 ? b1 : b0;
            float2 f1 = p1 ? b0 : b1;
            float st = p1 ? g_tau[w] : -g_tau[w];
            float2 g0 = make_float2(fmaf(st, f1.x, f0.x), fmaf(st, f1.y, f0.y));
            float2 g1 = make_float2(fmaf(-st, f0.x, f1.x), fmaf(-st, f0.y, f1.y));
#pragma unroll
            for (int t = 0; t < (1 << j); t++) {
                float2 at = unpack2(a[t]);
                float2 hi = cmul(at, g1);
                float2 lo = cmul(at, g0);
                a[t + (1 << j)] = pack2(hi.x, hi.y);
                a[t]            = pack2(lo.x, lo.y);
            }
        }

        // Depth-0 lane gates (trash wires 6..9), then depth-0 perm2.
#pragma unroll
        for (int k = 6; k < 10; k++) {
            int mb = 1 << (9 - k);
            float tau = g_tau[k];
            float tt = (sub & mb) ? tau : -tau;
            ull t2 = pack2(tt, tt);
#pragma unroll
            for (int r = 0; r < 64; r++) {
                ull p = __shfl_xor_sync(FULL, a[r], mb);
                a[r] = f2fma(t2, p, a[r]);
            }
        }
#pragma unroll
        for (int r = 0; r < 64; r++) {
            if (__popc(r) & 1)
                a[r] = __shfl_xor_sync(FULL, a[r], 15);
        }

        // Depths 1..3: perm1 (register swap), fused (lane,reg) gate pairs,
        // bare reg gates on wires 4,5, perm2 (skipped at the final depth).
#pragma unroll 1
        for (int d = 1; d < 4; d++) {
            // perm1: flip all 6 register (latent) bits if p1.
#pragma unroll
            for (int r = 0; r < 32; r++) {
                ull t0 = a[r], t1 = a[63 - r];
                a[r]      = p1 ? t1 : t0;
                a[63 - r] = p1 ? t0 : t1;
            }
            // Fused pairs: lane wire (6+q) with register wire q, q = 0..3.
            // Element-granular: apply the lane gate to both members of a
            // register pair, then the register gate to the pair. Gates act on
            // distinct wires (commute), and the lane gate is diagonal in the
            // register index, so this schedule is exact.
#pragma unroll
            for (int q = 0; q < 4; q++) {
                int lw = 6 + q;                  // lane wire
                int mb = 1 << (9 - lw);          // lane mask (8,4,2,1)
                float tauL = g_tau[d * 10 + lw];
                float tt = (sub & mb) ? tauL : -tauL;
                ull t2 = pack2(tt, tt);
                int m = 1 << (5 - q);            // register mask (32,16,8,4)
                float tauR = g_tau[d * 10 + q];
                ull qB = pack2(tauR, tauR), nqB = pack2(-tauR, -tauR);
#pragma unroll
                for (int r = 0; r < 64; r++) {
                    if (!(r & m)) {
                        int r1 = r | m;
                        ull pA = __shfl_xor_sync(FULL, a[r], mb);
                        a[r]  = f2fma(t2, pA, a[r]);
                        ull pB = __shfl_xor_sync(FULL, a[r1], mb);
                        a[r1] = f2fma(t2, pB, a[r1]);
                        ull t0 = a[r];
                        a[r]  = f2fma(nqB, a[r1], t0);
                        a[r1] = f2fma(qB, t0, a[r1]);
                    }
                }
            }
            // Bare register gates: wires 4 (bit 1) and 5 (bit 0).
#pragma unroll
            for (int k = 4; k < 6; k++) {
                int m = 1 << (5 - k);
                float tau = g_tau[d * 10 + k];
                ull tq = pack2(tau, tau), ntq = pack2(-tau, -tau);
#pragma unroll
                for (int r = 0; r < 64; r++) {
                    if (!(r & m)) {
                        int r1 = r | m;
                        ull a0 = a[r];
                        a[r]  = f2fma(ntq, a[r1], a0);
                        a[r1] = f2fma(tq, a0, a[r1]);
                    }
                }
            }
            // perm2: flip trash (lane) bits where popc(r) odd. Skipped on the
            // final depth (folded into the <Z> sign as S_even - S_odd).
            if (d != 3) {
#pragma unroll
                for (int r = 0; r < 64; r++) {
                    if (__popc(r) & 1)
                        a[r] = __shfl_xor_sync(FULL, a[r], 15);
                }
            }
        }

        // <Z> on trash wires 6..9 (sub bits 3..0), final perm2 + global scale
        // absorbed: Z_b = sign_b(sub) * (S_even - S_odd) * (prod cos)^2.
        ull ae = pack2(0.f, 0.f), ao = pack2(0.f, 0.f);
#pragma unroll
        for (int r = 0; r < 64; r++) {
            if (__popc(r) & 1) ao = f2fma(a[r], a[r], ao);
            else               ae = f2fma(a[r], a[r], ae);
        }
        float2 fe = unpack2(ae), fo = unpack2(ao);
        float sd = ((fe.x + fe.y) - (fo.x + fo.y)) * g_scale[0];

        // Signed Walsh butterfly over the 4 sub bits: after 4 levels, lane s
        // holds sum_t (-1)^{popc(s&t)} sd(t); lanes s = 1<<bit carry <Z>.
#pragma unroll
        for (int off = 1; off <= 8; off <<= 1) {
            float p = __shfl_xor_sync(FULL, sd, off);
            sd = (sub & off) ? (p - sd) : (sd + p);
        }
        if (__popc(sub) == 1 && event < B) {
            int bit = 31 - __clz(sub);       // sub = 1<<bit; output j = 3-bit
            out[(size_t)5 * B + (size_t)event * 4 + (3 - bit)] = sd;
        }
    } else {
        // ---------------- met + ele + mu: one thread per event ----------------
        int e = (blockIdx.x - nJetBlocks) * 64 + threadIdx.x;
        if (e >= B) return;
        const float* xr = x + (size_t)e * 56;

        {   // met (n=1): <Z> = cos(w)cos(pt) - sin(w)sin(pt)cos(phi)
            float sp, cp;
            __sincosf(xr[0], &sp, &cp);
            float cf = __cosf(xr[1]);
            out[e] = g_met[1] * cp - g_met[0] * sp * cf;
        }
        float o0, o1;
        sim4(xr, 2, 6, 10, &g_tau[40], g_scale[1], o0, o1);
        out[(size_t)B + (size_t)e * 2 + 0] = o0;
        out[(size_t)B + (size_t)e * 2 + 1] = o1;
        sim4(xr, 14, 18, 22, &g_tau[44], g_scale[2], o0, o1);
        out[(size_t)3 * B + (size_t)e * 2 + 0] = o0;
        out[(size_t)3 * B + (size_t)e * 2 + 1] = o1;
    }
}

extern "C" void kernel_launch(void* const* d_in, const int* in_sizes, int n_in,
                              void* d_out, int out_size) {
    const float* x     = (const float*)d_in[0];
    const float* met_w = (const float*)d_in[1];
    const float* ele_w = (const float*)d_in[2];
    const float* mu_w  = (const float*)d_in[3];
    const float* jet_w = (const float*)d_in[4];
    int B = in_sizes[0] / 56;
    int nJetBlocks = (B + 3) / 4;          // 2 warps/block, 2 events/warp
    int nSmallBlocks = (B + 63) / 64;      // 1 thread/event for met/ele/mu
    prep_kernel<<<1, 32>>>(met_w, ele_w, mu_w, jet_w);
    qae_kernel<<<nJetBlocks + nSmallBlocks, 64>>>(
        x, (float*)d_out, B, nJetBlocks);
}

// round 11
// speedup vs baseline: 7.8863x; 1.0645x over previous
#include <cuda_runtime.h>

#define FULL 0xFFFFFFFFu
typedef unsigned long long ull;

// Precomputed gate parameters (weights are batch-uniform):
//   g_tau[0..39]  = tan(jet_w/2),  g_tau[40..43] = tan(ele_w/2),
//   g_tau[44..47] = tan(mu_w/2)
//   g_scale[0..2] = (prod cos(w/2))^2 for jet / ele / mu  (ALL gates included)
//   g_met[0..1]   = sin(met_w), cos(met_w)
__device__ float g_tau[48];
__device__ float g_scale[3];
__device__ float g_met[2];

__global__ void prep_kernel(const float* __restrict__ met_w,
                            const float* __restrict__ ele_w,
                            const float* __restrict__ mu_w,
                            const float* __restrict__ jet_w) {
    int t = threadIdx.x;
    int lane = t & 31;
    if (t < 32) {
        // Warp 0: jet gates. Lane handles gate 'lane', lanes 0-7 also 32+lane.
        float c_all;
        {
            float s, c; __sincosf(0.5f * jet_w[lane], &s, &c);
            g_tau[lane] = __fdividef(s, c);
            c_all = c;
        }
        if (lane < 8) {
            int g = 32 + lane;
            float s, c; __sincosf(0.5f * jet_w[g], &s, &c);
            g_tau[g] = __fdividef(s, c);
            c_all *= c;
        }
#pragma unroll
        for (int off = 16; off >= 1; off >>= 1)
            c_all *= __shfl_xor_sync(FULL, c_all, off);
        if (lane == 0) g_scale[0] = c_all * c_all;
    } else {
        // Warp 1: ele (lanes 0-3), mu (lanes 4-7), met (lane 8).
        float c_all = 1.f;
        if (lane < 4) {
            float s, c; __sincosf(0.5f * ele_w[lane], &s, &c);
            g_tau[40 + lane] = __fdividef(s, c);
            c_all = c;
        } else if (lane < 8) {
            float s, c; __sincosf(0.5f * mu_w[lane - 4], &s, &c);
            g_tau[44 + (lane - 4)] = __fdividef(s, c);
            c_all = c;
        }
        c_all *= __shfl_xor_sync(FULL, c_all, 1);
        c_all *= __shfl_xor_sync(FULL, c_all, 2);
        if (lane == 0) g_scale[1] = c_all * c_all;
        if (lane == 4) g_scale[2] = c_all * c_all;
        if (lane == 8) {
            float s, c; __sincosf(met_w[0], &s, &c);
            g_met[0] = s; g_met[1] = c;
        }
    }
}

// ---------- packed f32x2 helpers (Blackwell paired-FP32 path) ----------
__device__ __forceinline__ ull pack2(float x, float y) {
    ull r; asm("mov.b64 %0,{%1,%2};" : "=l"(r) : "f"(x), "f"(y)); return r;
}
__device__ __forceinline__ float2 unpack2(ull v) {
    float2 r; asm("mov.b64 {%0,%1},%2;" : "=f"(r.x), "=f"(r.y) : "l"(v)); return r;
}
__device__ __forceinline__ ull swap2(ull v) {              // (x,y) -> (y,x)
    float2 t = unpack2(v); return pack2(t.y, t.x);
}
__device__ __forceinline__ ull f2mul(ull a, ull b) {
    ull d; asm("mul.rn.f32x2 %0,%1,%2;" : "=l"(d) : "l"(a), "l"(b)); return d;
}
__device__ __forceinline__ ull f2fma(ull a, ull b, ull c) {  // a*b + c
    ull d; asm("fma.rn.f32x2 %0,%1,%2,%3;" : "=l"(d) : "l"(a), "l"(b), "l"(c)); return d;
}

__device__ __forceinline__ float2 cmul(float2 a, float2 b) {
    return make_float2(fmaf(a.x, b.x, -a.y * b.y), fmaf(a.x, b.y, a.y * b.x));
}

// Column 0 of RZ(phi)*RY(pt)*RX(eta) applied to |0>.
__device__ __forceinline__ void wire_u(float pt, float eta, float phi,
                                       float2& u0, float2& u1) {
    float se, ce, sy, cy, sz, cz;
    __sincosf(0.5f * eta, &se, &ce);
    __sincosf(0.5f * pt, &sy, &cy);
    __sincosf(0.5f * phi, &sz, &cz);
    float2 b0 = make_float2(cy * ce, sy * se);
    float2 b1 = make_float2(sy * ce, -cy * se);
    u0 = cmul(make_float2(cz, -sz), b0);
    u1 = cmul(make_float2(cz, sz), b1);
}

// width-16 broadcast of a float2 held lane-wise
__device__ __forceinline__ float2 bc16(float vx, float vy, int src) {
    float2 r;
    r.x = __shfl_sync(FULL, vx, src, 16);
    r.y = __shfl_sync(FULL, vy, src, 16);
    return r;
}

// 4-qubit QAE block (ele / mu): latent=[0,1], trash=[2,3], depth=1.
__device__ __forceinline__ void sim4(const float* __restrict__ xr,
                                     int pt_off, int eta_off, int phi_off,
                                     const float* __restrict__ taus, float sc2,
                                     float& o0, float& o1) {
    float2 u0[4], u1[4];
#pragma unroll
    for (int k = 0; k < 4; k++)
        wire_u(xr[pt_off + k], xr[eta_off + k], xr[phi_off + k], u0[k], u1[k]);

    float2 a[16];
    a[0] = make_float2(1.f, 0.f);
#pragma unroll
    for (int j = 0; j < 4; j++) {
        int wk = 3 - j;
#pragma unroll
        for (int t = 0; t < (1 << j); t++) {
            a[t + (1 << j)] = cmul(a[t], u1[wk]);
            a[t]            = cmul(a[t], u0[wk]);
        }
    }
    // perm1: bits {3,2} ^= parity(bits {1,0})
    {
        float2 t;
        t = a[1];  a[1]  = a[13]; a[13] = t;
        t = a[2];  a[2]  = a[14]; a[14] = t;
        t = a[5];  a[5]  = a[9];  a[9]  = t;
        t = a[6];  a[6]  = a[10]; a[10] = t;
    }
#pragma unroll
    for (int k = 0; k < 4; k++) {
        float tau = taus[k];
        int m = 1 << (3 - k);
#pragma unroll
        for (int i = 0; i < 16; i++) {
            if (!(i & m)) {
                int i1 = i | m;
                float2 a0 = a[i], a1v = a[i1];
                a[i]  = make_float2(fmaf(-tau, a1v.x, a0.x), fmaf(-tau, a1v.y, a0.y));
                a[i1] = make_float2(fmaf(tau, a0.x, a1v.x), fmaf(tau, a0.y, a1v.y));
            }
        }
    }
    // perm2: bits {1,0} ^= parity(bits {3,2})
    {
        float2 t;
        t = a[4]; a[4] = a[7];  a[7]  = t;
        t = a[5]; a[5] = a[6];  a[6]  = t;
        t = a[8]; a[8] = a[11]; a[11] = t;
        t = a[9]; a[9] = a[10]; a[10] = t;
    }
    float r0 = 0.f, r1 = 0.f;
#pragma unroll
    for (int i = 0; i < 16; i++) {
        float p = fmaf(a[i].x, a[i].x, a[i].y * a[i].y);
        r0 += ((i >> 1) & 1) ? -p : p;
        r1 += (i & 1) ? -p : p;
    }
    o0 = r0 * sc2;
    o1 = r1 * sc2;
}

__global__ __launch_bounds__(64, 6)
void qae_kernel(const float* __restrict__ x,
                float* __restrict__ out,
                int B, int nJetBlocks) {
    if ((int)blockIdx.x < nJetBlocks) {
        // ================= jet: 2 events per warp, n=10 qubits =================
        // Amplitude index (10 bits): lane bits 0..3 (sub) = trash wires 9..6;
        // register bits r0..r5 = latent wires 5..0. Lane bit 4 = event select.
        int warpId = blockIdx.x * 2 + (threadIdx.x >> 5);
        if (warpId * 2 >= B) return;
        int lane = threadIdx.x & 31;
        int sub  = lane & 15;
        int half = lane >> 4;
        int event = warpId * 2 + half;
        int evc = event < B ? event : B - 1;        // clamp loads for odd B
        const float* xr = x + (size_t)evc * 56;

        // Per-wire encoding column: lanes sub 0..9 of each half compute; values
        // broadcast on demand via width-16 shfl.
        int kk = sub < 10 ? sub : 0;
        float2 myu0, myu1;
        wire_u(xr[26 + kk], xr[36 + kk], xr[46 + kk], myu0, myu1);

        // Lane-bit part of the tensor product: sub bit m <-> trash wire 9-m.
        float2 pl = make_float2(1.f, 0.f);
#pragma unroll
        for (int m = 0; m < 4; m++) {
            int w = 9 - m;
            float2 b0 = bc16(myu0.x, myu0.y, w);
            float2 b1 = bc16(myu1.x, myu1.y, w);
            float2 sel = ((sub >> m) & 1) ? b1 : b0;
            pl = cmul(pl, sel);
        }

        bool p1 = (__popc(sub) & 1) != 0;   // parity of trash bits

        // Register-bit part via doubling: reg bit j <-> latent wire 5-j.
        // Folds: (a) depth-0 perm1 -> factor-role swap when p1;
        //        (b) depth-0 latent RYs -> factor rotation with sign s.
        // Complex multiply done in packed f32x2:
        //   cmul(a,g) = f2fma(swap(a), (-g.y, g.y), f2mul(a, (g.x, g.x)))
        ull a[64];
        a[0] = pack2(pl.x, pl.y);
#pragma unroll
        for (int j = 0; j < 6; j++) {
            int w = 5 - j;
            float2 b0 = bc16(myu0.x, myu0.y, w);
            float2 b1 = bc16(myu1.x, myu1.y, w);
            float2 f0 = p1 ? b1 : b0;
            float2 f1 = p1 ? b0 : b1;
            float st = p1 ? g_tau[w] : -g_tau[w];
            float2 g0 = make_float2(fmaf(st, f1.x, f0.x), fmaf(st, f1.y, f0.y));
            float2 g1 = make_float2(fmaf(-st, f0.x, f1.x), fmaf(-st, f0.y, f1.y));
            ull g0R = pack2(g0.x, g0.x), g0I = pack2(-g0.y, g0.y);
            ull g1R = pack2(g1.x, g1.x), g1I = pack2(-g1.y, g1.y);
#pragma unroll
            for (int t = 0; t < (1 << j); t++) {
                ull at = a[t];
                ull sw = swap2(at);
                a[t + (1 << j)] = f2fma(sw, g1I, f2mul(at, g1R));
                a[t]            = f2fma(sw, g0I, f2mul(at, g0R));
            }
        }

        // Depth-0 lane gates (trash wires 6..9), then depth-0 perm2.
#pragma unroll
        for (int k = 6; k < 10; k++) {
            int mb = 1 << (9 - k);
            float tau = g_tau[k];
            float tt = (sub & mb) ? tau : -tau;
            ull t2 = pack2(tt, tt);
#pragma unroll
            for (int r = 0; r < 64; r++) {
                ull p = __shfl_xor_sync(FULL, a[r], mb);
                a[r] = f2fma(t2, p, a[r]);
            }
        }
#pragma unroll
        for (int r = 0; r < 64; r++) {
            if (__popc(r) & 1)
                a[r] = __shfl_xor_sync(FULL, a[r], 15);
        }

        // Depths 1..3: perm1, fused (lane,reg) pairs, bare reg gates, perm2
        // (perm2 at the final depth is folded into the measurement sign).
#pragma unroll 1
        for (int d = 1; d < 4; d++) {
            // perm1: flip all 6 register (latent) bits if p1.
#pragma unroll
            for (int r = 0; r < 32; r++) {
                ull t0 = a[r], t1 = a[63 - r];
                a[r]      = p1 ? t1 : t0;
                a[63 - r] = p1 ? t0 : t1;
            }
            // Fused pairs: lane wire (6+q) with register wire q, q = 0..3.
#pragma unroll
            for (int q = 0; q < 4; q++) {
                int lw = 6 + q;
                int mb = 1 << (9 - lw);
                float tauL = g_tau[d * 10 + lw];
                float tt = (sub & mb) ? tauL : -tauL;
                ull t2 = pack2(tt, tt);
                int m = 1 << (5 - q);
                float tauR = g_tau[d * 10 + q];
                ull qB = pack2(tauR, tauR), nqB = pack2(-tauR, -tauR);
#pragma unroll
                for (int r = 0; r < 64; r++) {
                    if (!(r & m)) {
                        int r1 = r | m;
                        ull pA = __shfl_xor_sync(FULL, a[r], mb);
                        a[r]  = f2fma(t2, pA, a[r]);
                        ull pB = __shfl_xor_sync(FULL, a[r1], mb);
                        a[r1] = f2fma(t2, pB, a[r1]);
                        ull t0 = a[r];
                        a[r]  = f2fma(nqB, a[r1], t0);
                        a[r1] = f2fma(qB, t0, a[r1]);
                    }
                }
            }
            // Bare register gates: wires 4 and 5.
#pragma unroll
            for (int k = 4; k < 6; k++) {
                int m = 1 << (5 - k);
                float tau = g_tau[d * 10 + k];
                ull tq = pack2(tau, tau), ntq = pack2(-tau, -tau);
#pragma unroll
                for (int r = 0; r < 64; r++) {
                    if (!(r & m)) {
                        int r1 = r | m;
                        ull a0 = a[r];
                        a[r]  = f2fma(ntq, a[r1], a0);
                        a[r1] = f2fma(tq, a0, a[r1]);
                    }
                }
            }
            // perm2: flip trash (lane) bits where popc(r) odd. Skipped on the
            // final depth (folded into the <Z> sign as S_even - S_odd).
            if (d != 3) {
#pragma unroll
                for (int r = 0; r < 64; r++) {
                    if (__popc(r) & 1)
                        a[r] = __shfl_xor_sync(FULL, a[r], 15);
                }
            }
        }

        // <Z> on trash wires 6..9 (sub bits 3..0), final perm2 + global scale
        // absorbed: Z_b = sign_b(sub) * (S_even - S_odd) * (prod cos)^2.
        ull ae = pack2(0.f, 0.f), ao = pack2(0.f, 0.f);
#pragma unroll
        for (int r = 0; r < 64; r++) {
            if (__popc(r) & 1) ao = f2fma(a[r], a[r], ao);
            else               ae = f2fma(a[r], a[r], ae);
        }
        float2 fe = unpack2(ae), fo = unpack2(ao);
        float sd = ((fe.x + fe.y) - (fo.x + fo.y)) * g_scale[0];

        // Signed Walsh butterfly over the 4 sub bits: after 4 levels, lane s
        // holds sum_t (-1)^{popc(s&t)} sd(t); lanes s = 1<<bit carry <Z>.
#pragma unroll
        for (int off = 1; off <= 8; off <<= 1) {
            float p = __shfl_xor_sync(FULL, sd, off);
            sd = (sub & off) ? (p - sd) : (sd + p);
        }
        if (__popc(sub) == 1 && event < B) {
            int bit = 31 - __clz(sub);       // sub = 1<<bit; output j = 3-bit
            out[(size_t)5 * B + (size_t)event * 4 + (3 - bit)] = sd;
        }
    } else {
        // ---------------- met + ele + mu: one thread per event ----------------
        int e = (blockIdx.x - nJetBlocks) * 64 + threadIdx.x;
        if (e >= B) return;
        const float* xr = x + (size_t)e * 56;

        {   // met (n=1): <Z> = cos(w)cos(pt) - sin(w)sin(pt)cos(phi)
            float sp, cp;
            __sincosf(xr[0], &sp, &cp);
            float cf = __cosf(xr[1]);
            out[e] = g_met[1] * cp - g_met[0] * sp * cf;
        }
        float o0, o1;
        sim4(xr, 2, 6, 10, &g_tau[40], g_scale[1], o0, o1);
        out[(size_t)B + (size_t)e * 2 + 0] = o0;
        out[(size_t)B + (size_t)e * 2 + 1] = o1;
        sim4(xr, 14, 18, 22, &g_tau[44], g_scale[2], o0, o1);
        out[(size_t)3 * B + (size_t)e * 2 + 0] = o0;
        out[(size_t)3 * B + (size_t)e * 2 + 1] = o1;
    }
}

extern "C" void kernel_launch(void* const* d_in, const int* in_sizes, int n_in,
                              void* d_out, int out_size) {
    const float* x     = (const float*)d_in[0];
    const float* met_w = (const float*)d_in[1];
    const float* ele_w = (const float*)d_in[2];
    const float* mu_w  = (const float*)d_in[3];
    const float* jet_w = (const float*)d_in[4];
    int B = in_sizes[0] / 56;
    int nJetBlocks = (B + 3) / 4;          // 2 warps/block, 2 events/warp
    int nSmallBlocks = (B + 63) / 64;      // 1 thread/event for met/ele/mu
    prep_kernel<<<1, 64>>>(met_w, ele_w, mu_w, jet_w);
    qae_kernel<<<nJetBlocks + nSmallBlocks, 64>>>(
        x, (float*)d_out, B, nJetBlocks);
}

// round 12
// speedup vs baseline: 8.3754x; 1.0620x over previous
#include <cuda_runtime.h>

#define FULL 0xFFFFFFFFu
typedef unsigned long long ull;

// ---------- packed f32x2 helpers (Blackwell paired-FP32 path) ----------
__device__ __forceinline__ ull pack2(float x, float y) {
    ull r; asm("mov.b64 %0,{%1,%2};" : "=l"(r) : "f"(x), "f"(y)); return r;
}
__device__ __forceinline__ float2 unpack2(ull v) {
    float2 r; asm("mov.b64 {%0,%1},%2;" : "=f"(r.x), "=f"(r.y) : "l"(v)); return r;
}
__device__ __forceinline__ ull swap2(ull v) {              // (x,y) -> (y,x)
    float2 t = unpack2(v); return pack2(t.y, t.x);
}
__device__ __forceinline__ ull f2mul(ull a, ull b) {
    ull d; asm("mul.rn.f32x2 %0,%1,%2;" : "=l"(d) : "l"(a), "l"(b)); return d;
}
__device__ __forceinline__ ull f2fma(ull a, ull b, ull c) {  // a*b + c
    ull d; asm("fma.rn.f32x2 %0,%1,%2,%3;" : "=l"(d) : "l"(a), "l"(b), "l"(c)); return d;
}

__device__ __forceinline__ float2 cmul(float2 a, float2 b) {
    return make_float2(fmaf(a.x, b.x, -a.y * b.y), fmaf(a.x, b.y, a.y * b.x));
}

// Column 0 of RZ(phi)*RY(pt)*RX(eta) applied to |0>.
__device__ __forceinline__ void wire_u(float pt, float eta, float phi,
                                       float2& u0, float2& u1) {
    float se, ce, sy, cy, sz, cz;
    __sincosf(0.5f * eta, &se, &ce);
    __sincosf(0.5f * pt, &sy, &cy);
    __sincosf(0.5f * phi, &sz, &cz);
    float2 b0 = make_float2(cy * ce, sy * se);
    float2 b1 = make_float2(sy * ce, -cy * se);
    u0 = cmul(make_float2(cz, -sz), b0);
    u1 = cmul(make_float2(cz, sz), b1);
}

// width-16 broadcast of a float2 held lane-wise
__device__ __forceinline__ float2 bc16(float vx, float vy, int src) {
    float2 r;
    r.x = __shfl_sync(FULL, vx, src, 16);
    r.y = __shfl_sync(FULL, vy, src, 16);
    return r;
}

// 4-qubit QAE block (ele / mu): latent=[0,1], trash=[2,3], depth=1.
// RY gates tau-factorized; taus + scale computed inline (cheap at n=4).
__device__ __forceinline__ void sim4(const float* __restrict__ xr,
                                     int pt_off, int eta_off, int phi_off,
                                     const float* __restrict__ w,
                                     float& o0, float& o1) {
    float2 u0[4], u1[4];
#pragma unroll
    for (int k = 0; k < 4; k++)
        wire_u(xr[pt_off + k], xr[eta_off + k], xr[phi_off + k], u0[k], u1[k]);

    float2 a[16];
    a[0] = make_float2(1.f, 0.f);
#pragma unroll
    for (int j = 0; j < 4; j++) {
        int wk = 3 - j;
#pragma unroll
        for (int t = 0; t < (1 << j); t++) {
            a[t + (1 << j)] = cmul(a[t], u1[wk]);
            a[t]            = cmul(a[t], u0[wk]);
        }
    }
    // perm1: bits {3,2} ^= parity(bits {1,0})
    {
        float2 t;
        t = a[1];  a[1]  = a[13]; a[13] = t;
        t = a[2];  a[2]  = a[14]; a[14] = t;
        t = a[5];  a[5]  = a[9];  a[9]  = t;
        t = a[6];  a[6]  = a[10]; a[10] = t;
    }
    float sc = 1.f;
#pragma unroll
    for (int k = 0; k < 4; k++) {
        float s, c;
        __sincosf(0.5f * w[k], &s, &c);
        float tau = __fdividef(s, c);
        sc *= c;
        int m = 1 << (3 - k);
#pragma unroll
        for (int i = 0; i < 16; i++) {
            if (!(i & m)) {
                int i1 = i | m;
                float2 a0 = a[i], a1v = a[i1];
                a[i]  = make_float2(fmaf(-tau, a1v.x, a0.x), fmaf(-tau, a1v.y, a0.y));
                a[i1] = make_float2(fmaf(tau, a0.x, a1v.x), fmaf(tau, a0.y, a1v.y));
            }
        }
    }
    // perm2: bits {1,0} ^= parity(bits {3,2})
    {
        float2 t;
        t = a[4]; a[4] = a[7];  a[7]  = t;
        t = a[5]; a[5] = a[6];  a[6]  = t;
        t = a[8]; a[8] = a[11]; a[11] = t;
        t = a[9]; a[9] = a[10]; a[10] = t;
    }
    float r0 = 0.f, r1 = 0.f;
#pragma unroll
    for (int i = 0; i < 16; i++) {
        float p = fmaf(a[i].x, a[i].x, a[i].y * a[i].y);
        r0 += ((i >> 1) & 1) ? -p : p;
        r1 += (i & 1) ? -p : p;
    }
    float sc2 = sc * sc;
    o0 = r0 * sc2;
    o1 = r1 * sc2;
}

__global__ __launch_bounds__(64, 6)
void qae_kernel(const float* __restrict__ x,
                const float* __restrict__ met_w,
                const float* __restrict__ ele_w,
                const float* __restrict__ mu_w,
                const float* __restrict__ jet_w,
                float* __restrict__ out,
                int B, int nJetBlocks) {
    __shared__ float s_tau[40];
    __shared__ float s_scale;

    if ((int)blockIdx.x < nJetBlocks) {
        // ================= jet: 2 events per warp, n=10 qubits =================
        // Amplitude index (10 bits): lane bits 0..3 (sub) = trash wires 9..6;
        // register bits r0..r5 = latent wires 5..0. Lane bit 4 = event select.
        int warp = threadIdx.x >> 5;
        int warpId = blockIdx.x * 2 + warp;
        int lane = threadIdx.x & 31;
        int sub  = lane & 15;
        int half = lane >> 4;
        int event = warpId * 2 + half;
        int evc = event < B ? event : B - 1;        // clamp (no early return:
        const float* xr = x + (size_t)evc * 56;     //  block-wide barrier below)

        // Per-wire encoding column: lanes sub 0..9 of each half compute; values
        // broadcast on demand via width-16 shfl. (tau-free prologue)
        int kk = sub < 10 ? sub : 0;
        float2 myu0, myu1;
        wire_u(xr[26 + kk], xr[36 + kk], xr[46 + kk], myu0, myu1);

        // Lane-bit part of the tensor product: sub bit m <-> trash wire 9-m.
        float2 pl = make_float2(1.f, 0.f);
#pragma unroll
        for (int m = 0; m < 4; m++) {
            int w = 9 - m;
            float2 b0 = bc16(myu0.x, myu0.y, w);
            float2 b1 = bc16(myu1.x, myu1.y, w);
            float2 sel = ((sub >> m) & 1) ? b1 : b0;
            pl = cmul(pl, sel);
        }

        // Warp 0 computes the 40 jet taus + (prod cos)^2 into shared memory
        // while warp 1 finishes its prologue.
        if (warp == 0) {
            float c_all;
            {
                float s, c; __sincosf(0.5f * jet_w[lane], &s, &c);
                s_tau[lane] = __fdividef(s, c);
                c_all = c;
            }
            if (lane < 8) {
                float s, c; __sincosf(0.5f * jet_w[32 + lane], &s, &c);
                s_tau[32 + lane] = __fdividef(s, c);
                c_all *= c;
            }
#pragma unroll
            for (int off = 16; off >= 1; off >>= 1)
                c_all *= __shfl_xor_sync(FULL, c_all, off);
            if (lane == 0) s_scale = c_all * c_all;
        }
        __syncthreads();

        bool p1 = (__popc(sub) & 1) != 0;   // parity of trash bits

        // Register-bit part via doubling: reg bit j <-> latent wire 5-j.
        // Folds: (a) depth-0 perm1 -> factor-role swap when p1;
        //        (b) depth-0 latent RYs -> factor rotation with sign s.
        // Complex multiply in packed f32x2:
        //   cmul(a,g) = f2fma(swap(a), (-g.y, g.y), f2mul(a, (g.x, g.x)))
        ull a[64];
        a[0] = pack2(pl.x, pl.y);
#pragma unroll
        for (int j = 0; j < 6; j++) {
            int w = 5 - j;
            float2 b0 = bc16(myu0.x, myu0.y, w);
            float2 b1 = bc16(myu1.x, myu1.y, w);
            float2 f0 = p1 ? b1 : b0;
            float2 f1 = p1 ? b0 : b1;
            float st = p1 ? s_tau[w] : -s_tau[w];
            float2 g0 = make_float2(fmaf(st, f1.x, f0.x), fmaf(st, f1.y, f0.y));
            float2 g1 = make_float2(fmaf(-st, f0.x, f1.x), fmaf(-st, f0.y, f1.y));
            ull g0R = pack2(g0.x, g0.x), g0I = pack2(-g0.y, g0.y);
            ull g1R = pack2(g1.x, g1.x), g1I = pack2(-g1.y, g1.y);
#pragma unroll
            for (int t = 0; t < (1 << j); t++) {
                ull at = a[t];
                ull sw = swap2(at);
                a[t + (1 << j)] = f2fma(sw, g1I, f2mul(at, g1R));
                a[t]            = f2fma(sw, g0I, f2mul(at, g0R));
            }
        }

        // Depth-0 lane gates (trash wires 6..9), then depth-0 perm2.
#pragma unroll
        for (int k = 6; k < 10; k++) {
            int mb = 1 << (9 - k);
            float tau = s_tau[k];
            float tt = (sub & mb) ? tau : -tau;
            ull t2 = pack2(tt, tt);
#pragma unroll
            for (int r = 0; r < 64; r++) {
                ull p = __shfl_xor_sync(FULL, a[r], mb);
                a[r] = f2fma(t2, p, a[r]);
            }
        }
#pragma unroll
        for (int r = 0; r < 64; r++) {
            if (__popc(r) & 1)
                a[r] = __shfl_xor_sync(FULL, a[r], 15);
        }

        // Depths 1..3: perm1, 10 RY gates (interleaved lane/reg order so the
        // MIO and FMA pipes overlap), perm2 (folded into signs at d=3).
        const int korder[10] = {6, 0, 1, 7, 2, 3, 8, 4, 5, 9};
#pragma unroll 1
        for (int d = 1; d < 4; d++) {
            // perm1: flip all 6 register (latent) bits if p1.
#pragma unroll
            for (int r = 0; r < 32; r++) {
                ull t0 = a[r], t1 = a[63 - r];
                a[r]      = p1 ? t1 : t0;
                a[63 - r] = p1 ? t0 : t1;
            }
#pragma unroll
            for (int kq = 0; kq < 10; kq++) {
                int k = korder[kq];
                float tau = s_tau[d * 10 + k];
                if (k < 6) {                     // register bit j = 5-k
                    int m = 1 << (5 - k);
                    ull tq = pack2(tau, tau), ntq = pack2(-tau, -tau);
#pragma unroll
                    for (int r = 0; r < 64; r++) {
                        if (!(r & m)) {
                            int r1 = r | m;
                            ull a0 = a[r];
                            a[r]  = f2fma(ntq, a[r1], a0);
                            a[r1] = f2fma(tq, a0, a[r1]);
                        }
                    }
                } else {                         // lane bit (9-k): shfl pairing
                    int mb = 1 << (9 - k);
                    float tt = (sub & mb) ? tau : -tau;
                    ull t2 = pack2(tt, tt);
#pragma unroll
                    for (int r = 0; r < 64; r++) {
                        ull p = __shfl_xor_sync(FULL, a[r], mb);
                        a[r] = f2fma(t2, p, a[r]);
                    }
                }
            }
            // perm2: flip trash (lane) bits where popc(r) odd. Skipped on the
            // final depth (folded into the <Z> sign as S_even - S_odd).
            if (d != 3) {
#pragma unroll
                for (int r = 0; r < 64; r++) {
                    if (__popc(r) & 1)
                        a[r] = __shfl_xor_sync(FULL, a[r], 15);
                }
            }
        }

        // <Z> on trash wires 6..9 (sub bits 3..0), final perm2 + global scale
        // absorbed: Z_b = sign_b(sub) * (S_even - S_odd) * (prod cos)^2.
        ull ae = pack2(0.f, 0.f), ao = pack2(0.f, 0.f);
#pragma unroll
        for (int r = 0; r < 64; r++) {
            if (__popc(r) & 1) ao = f2fma(a[r], a[r], ao);
            else               ae = f2fma(a[r], a[r], ae);
        }
        float2 fe = unpack2(ae), fo = unpack2(ao);
        float sd = ((fe.x + fe.y) - (fo.x + fo.y)) * s_scale;

        // Signed Walsh butterfly over the 4 sub bits: after 4 levels, lane s
        // holds sum_t (-1)^{popc(s&t)} sd(t); lanes s = 1<<bit carry <Z>.
#pragma unroll
        for (int off = 1; off <= 8; off <<= 1) {
            float p = __shfl_xor_sync(FULL, sd, off);
            sd = (sub & off) ? (p - sd) : (sd + p);
        }
        if (__popc(sub) == 1 && event < B) {
            int bit = 31 - __clz(sub);       // sub = 1<<bit; output j = 3-bit
            out[(size_t)5 * B + (size_t)event * 4 + (3 - bit)] = sd;
        }
    } else {
        // ---------------- met + ele + mu: one thread per event ----------------
        int e = (blockIdx.x - nJetBlocks) * 64 + threadIdx.x;
        if (e >= B) return;
        const float* xr = x + (size_t)e * 56;

        {   // met (n=1): <Z> = cos(w)cos(pt) - sin(w)sin(pt)cos(phi)
            float sw, cw, sp, cp;
            __sincosf(met_w[0], &sw, &cw);
            __sincosf(xr[0], &sp, &cp);
            float cf = __cosf(xr[1]);
            out[e] = cw * cp - sw * sp * cf;
        }
        float o0, o1;
        sim4(xr, 2, 6, 10, ele_w, o0, o1);
        out[(size_t)B + (size_t)e * 2 + 0] = o0;
        out[(size_t)B + (size_t)e * 2 + 1] = o1;
        sim4(xr, 14, 18, 22, mu_w, o0, o1);
        out[(size_t)3 * B + (size_t)e * 2 + 0] = o0;
        out[(size_t)3 * B + (size_t)e * 2 + 1] = o1;
    }
}

extern "C" void kernel_launch(void* const* d_in, const int* in_sizes, int n_in,
                              void* d_out, int out_size) {
    const float* x     = (const float*)d_in[0];
    const float* met_w = (const float*)d_in[1];
    const float* ele_w = (const float*)d_in[2];
    const float* mu_w  = (const float*)d_in[3];
    const float* jet_w = (const float*)d_in[4];
    int B = in_sizes[0] / 56;
    int nJetBlocks = (B + 3) / 4;          // 2 warps/block, 2 events/warp
    int nSmallBlocks = (B + 63) / 64;      // 1 thread/event for met/ele/mu
    qae_kernel<<<nJetBlocks + nSmallBlocks, 64>>>(
        x, met_w, ele_w, mu_w, jet_w, (float*)d_out, B, nJetBlocks);
}